// round 14
// baseline (speedup 1.0000x reference)
#include <cuda_runtime.h>
#include <cuda_fp16.h>
#include <math.h>
#include <cstdint>

// Problem constants
#define D_MODEL 1024
#define N_BATCH 4
#define SEQ     4096
#define HEADS   16
#define HD      64
#define NH      (N_BATCH * HEADS)        // 64
#define M_TOTAL (N_BATCH * SEQ)          // 16384

typedef unsigned long long ull;
typedef __half hf;

// ---------------- scratch (device globals: no allocation allowed) ----------
__device__ float g_KV [NH * HD * HD];       // per-(n,h) KV[m][d] fp32 accum
__device__ hf    g_KVh[NH * HD * HD];       // fp16 copy for MMA
__device__ float g_KS [NH * HD];            // per-(n,h) K_sum[d]

__device__ hf g_Ah[M_TOTAL * D_MODEL];      // attn output (A of Wo GEMM)
__device__ hf g_Qh[M_TOTAL * D_MODEL];      // Q_lin fp16 [token][channel]
__device__ hf g_KT[D_MODEL * M_TOTAL];      // K_lin^T fp16 [channel][token]
__device__ hf g_VT[D_MODEL * M_TOTAL];      // V^T     fp16 [channel][token]
__device__ hf g_Wqh[D_MODEL * D_MODEL];
__device__ hf g_Wkh[D_MODEL * D_MODEL];
__device__ hf g_Wvh[D_MODEL * D_MODEL];
__device__ hf g_Woh[D_MODEL * D_MODEL];

// ---------------- ptx helpers ---------------------------------------------
__device__ __forceinline__ uint32_t smem_u32(const void* p) {
    uint32_t a;
    asm("{ .reg .u64 t; cvta.to.shared.u64 t, %1; cvt.u32.u64 %0, t; }" : "=r"(a) : "l"(p));
    return a;
}
__device__ __forceinline__ void cp_async16(uint32_t s, const void* g) {
    asm volatile("cp.async.cg.shared.global [%0], [%1], 16;" :: "r"(s), "l"(g));
}
__device__ __forceinline__ void cpa_commit() { asm volatile("cp.async.commit_group;" ::: "memory"); }
__device__ __forceinline__ void cpa_wait1()  { asm volatile("cp.async.wait_group 1;" ::: "memory"); }
__device__ __forceinline__ void cpa_wait0()  { asm volatile("cp.async.wait_group 0;" ::: "memory"); }

#define LDSM4(r, a) \
    asm volatile("ldmatrix.sync.aligned.m8n8.x4.shared.b16 {%0,%1,%2,%3}, [%4];" \
        : "=r"((r)[0]), "=r"((r)[1]), "=r"((r)[2]), "=r"((r)[3]) : "r"(a))

#define MMA16816(d, a, b) \
    asm volatile("mma.sync.aligned.m16n8k16.row.col.f32.f16.f16.f32 " \
        "{%0,%1,%2,%3}, {%4,%5,%6,%7}, {%8,%9}, {%0,%1,%2,%3};" \
        : "+f"((d)[0]), "+f"((d)[1]), "+f"((d)[2]), "+f"((d)[3]) \
        : "r"((a)[0]), "r"((a)[1]), "r"((a)[2]), "r"((a)[3]), \
          "r"((b)[0]), "r"((b)[1]))

// ldmatrix lane-offset generators (validated R5-R12), parametric in row stride
__device__ __forceinline__ uint32_t a_lane_off(int lane, int rowb) {
    return (uint32_t)((lane & 15) * rowb + ((lane >> 4) << 4));
}
__device__ __forceinline__ uint32_t b_lane_off(int lane, int rowb) {
    return (uint32_t)(((((lane >> 4) & 1) * 8 + (lane & 7)) * rowb)
                      + (((lane >> 3) & 1) << 4));
}
__device__ __forceinline__ uint32_t h2u(__half2 h) { return *(uint32_t*)&h; }

// ================= GEMM tiling constants ===================================
#define T_ROWB   80
#define T_BYTES  (128 * T_ROWB)          // 10240
#define ST_BYTES (2 * T_BYTES)           // 20480
#define OFF_AH   0
#define OFF_BH   T_BYTES
#define GSTAGES  3
#define SM_BIAS  (GSTAGES * ST_BYTES)    // 61440
#define SM_TOTAL (SM_BIAS + 512)
#define NCHUNK   (D_MODEL / 32)          // 32
#define TR_STRIDE 136                    // transpose buffer halves/row

// ---------------- B-only cp.async staging ----------------------------------
__device__ __forceinline__ void load_stage_B(
    uint32_t sb, const hf* __restrict__ Bh, int bcol0, int kt, int tid)
{
    const uint32_t st = sb + (uint32_t)(kt % GSTAGES) * ST_BYTES;
    const size_t kof = (size_t)kt * 32;
    #pragma unroll
    for (int v = 0; v < 2; v++) {
        const int idx = v * 256 + tid;
        const int r  = idx >> 2;
        const int cc = idx & 3;
        cp_async16(st + OFF_BH + (uint32_t)(r * T_ROWB + cc * 16),
                   Bh + (size_t)(bcol0 + r) * D_MODEL + kof + cc * 8);
    }
}

// ---------------- A fp32->fp16 register-staged STS --------------------------
__device__ __forceinline__ void sts_a16(char* smem, int buf, int ar, int ahalf,
                                        const float4* aN)
{
    hf* dst = (hf*)(smem + buf * ST_BYTES + OFF_AH + ar * T_ROWB + ahalf * 32);
    uint4 u0, u1;
    u0.x = h2u(__floats2half2_rn(aN[0].x, aN[0].y));
    u0.y = h2u(__floats2half2_rn(aN[0].z, aN[0].w));
    u0.z = h2u(__floats2half2_rn(aN[1].x, aN[1].y));
    u0.w = h2u(__floats2half2_rn(aN[1].z, aN[1].w));
    u1.x = h2u(__floats2half2_rn(aN[2].x, aN[2].y));
    u1.y = h2u(__floats2half2_rn(aN[2].z, aN[2].w));
    u1.z = h2u(__floats2half2_rn(aN[3].x, aN[3].y));
    u1.w = h2u(__floats2half2_rn(aN[3].z, aN[3].w));
    *(uint4*)dst       = u0;
    *(uint4*)(dst + 8) = u1;
}

// ================= batched projection GEMM (z = Q/K/V) =====================
// C[M,1024] = elu?(A_f32[M,1024] * W^T + bias); output fp16 normal (z=0)
// or fp16 transposed [channel][token] (z=1,2). A converted in-kernel.
// __launch_bounds__(256, 1): the A-staging registers (16) on top of the
// 64 accumulators overflow the 128-reg budget that (256,2) imposes -> R12's
// mainloop spills. 1 CTA/SM (255 regs) removes the spills; 8 warps still
// saturate the legacy HMMA pipe (validated at 1 CTA/SM in R5).
struct ProjParams {
    const float* A[3];
    const hf*    W[3];
    const float* bias[3];
    hf*          out[3];
};

__global__ __launch_bounds__(256, 1)
void gemm_proj(ProjParams P)
{
    extern __shared__ char smem[];
    const uint32_t sb = smem_u32(smem);
    const int tid  = threadIdx.x;
    const int lane = tid & 31;
    const int w    = tid >> 5;
    const int wm   = w >> 2;
    const int wn   = w & 3;
    const int z    = blockIdx.z;
    const int brow0 = blockIdx.y * 128;
    const int bcol0 = blockIdx.x * 128;

    const float* Af = P.A[z];
    const hf*    Bh = P.W[z];

    if (tid < 128) ((float*)(smem + SM_BIAS))[tid] = P.bias[z][bcol0 + tid];

    // A load mapping: thread -> (row, 16-float half-row)
    const int ar    = tid >> 1;
    const int ahalf = tid & 1;
    const float* Abase = Af + (size_t)(brow0 + ar) * D_MODEL + ahalf * 16;

    float c[4][4][4];
    #pragma unroll
    for (int mi = 0; mi < 4; mi++)
        #pragma unroll
        for (int ni = 0; ni < 4; ni++)
            #pragma unroll
            for (int q = 0; q < 4; q++) c[mi][ni][q] = 0.f;

    float4 aN[4];
    // prologue: stage 0 (LDG+STS now), stage 1 (LDG into regs)
    {
        const float4* p = (const float4*)Abase;
        float4 t0[4] = {p[0], p[1], p[2], p[3]};
        sts_a16(smem, 0, ar, ahalf, t0);
        load_stage_B(sb, Bh, bcol0, 0, tid);
        cpa_commit();
    }
    {
        const float4* p = (const float4*)(Abase + 32);
        aN[0] = p[0]; aN[1] = p[1]; aN[2] = p[2]; aN[3] = p[3];
        load_stage_B(sb, Bh, bcol0, 1, tid);
        cpa_commit();
    }

    const uint32_t a_lrow = a_lane_off(lane, T_ROWB);
    const uint32_t b_lrow = b_lane_off(lane, T_ROWB);

    for (int kt = 0; kt < NCHUNK; kt++) {
        cpa_wait1();
        __syncthreads();
        // STS A for stage kt+1 (loaded last iteration)
        if (kt + 1 < NCHUNK)
            sts_a16(smem, (kt + 1) % GSTAGES, ar, ahalf, aN);
        if (kt + 2 < NCHUNK)
            load_stage_B(sb, Bh, bcol0, kt + 2, tid);
        cpa_commit();
        // LDG A for stage kt+2 (consumed next iteration)
        if (kt + 2 < NCHUNK) {
            const float4* p = (const float4*)(Abase + (size_t)(kt + 2) * 32);
            aN[0] = p[0]; aN[1] = p[1]; aN[2] = p[2]; aN[3] = p[3];
        }

        const uint32_t st = sb + (uint32_t)(kt % GSTAGES) * ST_BYTES;
        #pragma unroll
        for (int ks = 0; ks < 2; ks++) {
            const uint32_t kb = ks * 32;
            uint32_t ah[4][4];
            #pragma unroll
            for (int mi = 0; mi < 4; mi++)
                LDSM4(ah[mi], st + OFF_AH
                      + (uint32_t)((wm * 64 + mi * 16) * T_ROWB) + a_lrow + kb);
            uint32_t bh[4][2];
            #pragma unroll
            for (int bi = 0; bi < 2; bi++) {
                uint32_t t4[4];
                LDSM4(t4, st + OFF_BH
                      + (uint32_t)((wn * 32 + bi * 16) * T_ROWB) + b_lrow + kb);
                bh[2 * bi][0] = t4[0]; bh[2 * bi][1] = t4[1];
                bh[2 * bi + 1][0] = t4[2]; bh[2 * bi + 1][1] = t4[3];
            }
            #pragma unroll
            for (int mi = 0; mi < 4; mi++)
                #pragma unroll
                for (int ni = 0; ni < 4; ni++)
                    MMA16816(c[mi][ni], ah[mi], bh[ni]);
        }
    }

    // ---------------- epilogue ----------------
    const float* sbias = (const float*)(smem + SM_BIAS);
    const int r0 = lane >> 2;
    const int c0 = (lane & 3) * 2;
    const int act = (z <= 1);
    hf* Ch = P.out[z];

    if (z != 0) {
        // transposed fp16 output [channel][token]
        __syncthreads();
        hf* TR = (hf*)smem;
        #pragma unroll
        for (int mi = 0; mi < 4; mi++) {
            const int m0 = wm * 64 + mi * 16 + r0;
            #pragma unroll
            for (int ni = 0; ni < 4; ni++) {
                const int n = wn * 32 + ni * 8 + c0;
                const float b0 = sbias[n], b1 = sbias[n + 1];
                float v0 = c[mi][ni][0] + b0;
                float v1 = c[mi][ni][1] + b1;
                float v2 = c[mi][ni][2] + b0;
                float v3 = c[mi][ni][3] + b1;
                if (act) {
                    v0 = (v0 > 0.f) ? (v0 + 1.f) : expf(v0);
                    v1 = (v1 > 0.f) ? (v1 + 1.f) : expf(v1);
                    v2 = (v2 > 0.f) ? (v2 + 1.f) : expf(v2);
                    v3 = (v3 > 0.f) ? (v3 + 1.f) : expf(v3);
                }
                TR[n * TR_STRIDE + m0]           = __float2half_rn(v0);
                TR[(n + 1) * TR_STRIDE + m0]     = __float2half_rn(v1);
                TR[n * TR_STRIDE + m0 + 8]       = __float2half_rn(v2);
                TR[(n + 1) * TR_STRIDE + m0 + 8] = __float2half_rn(v3);
            }
        }
        __syncthreads();
        for (int i = tid; i < 128 * 16; i += 256) {
            const int n = i >> 4, seg = i & 15;
            float4 val = *(float4*)&TR[n * TR_STRIDE + seg * 8];
            *(float4*)(Ch + (size_t)(bcol0 + n) * M_TOTAL + brow0 + seg * 8) = val;
        }
        return;
    }

    // normal fp16 output (Q_lin)
    #pragma unroll
    for (int mi = 0; mi < 4; mi++) {
        const int m = brow0 + wm * 64 + mi * 16 + r0;
        #pragma unroll
        for (int ni = 0; ni < 4; ni++) {
            const int n = wn * 32 + ni * 8 + c0;
            const float b0 = sbias[n], b1 = sbias[n + 1];
            float v0 = c[mi][ni][0] + b0;
            float v1 = c[mi][ni][1] + b1;
            float v2 = c[mi][ni][2] + b0;
            float v3 = c[mi][ni][3] + b1;
            v0 = (v0 > 0.f) ? (v0 + 1.f) : expf(v0);
            v1 = (v1 > 0.f) ? (v1 + 1.f) : expf(v1);
            v2 = (v2 > 0.f) ? (v2 + 1.f) : expf(v2);
            v3 = (v3 > 0.f) ? (v3 + 1.f) : expf(v3);
            *(__half2*)(Ch + (size_t)m * D_MODEL + bcol0 + n)       = __floats2half2_rn(v0, v1);
            *(__half2*)(Ch + (size_t)(m + 8) * D_MODEL + bcol0 + n) = __floats2half2_rn(v2, v3);
        }
    }
}

// ================= output GEMM (fp16 A via cp.async, fp32 out) =============
__device__ __forceinline__ void load_stage_AB(
    uint32_t sb, const hf* __restrict__ Ah, const hf* __restrict__ Bh,
    int brow0, int bcol0, int kt, int tid)
{
    const uint32_t st = sb + (uint32_t)(kt % GSTAGES) * ST_BYTES;
    const size_t kof = (size_t)kt * 32;
    #pragma unroll
    for (int v = 0; v < 2; v++) {
        const int idx = v * 256 + tid;
        const int r  = idx >> 2;
        const int cc = idx & 3;
        const uint32_t so = (uint32_t)(r * T_ROWB + cc * 16);
        cp_async16(st + OFF_AH + so, Ah + (size_t)(brow0 + r) * D_MODEL + kof + cc * 8);
        cp_async16(st + OFF_BH + so, Bh + (size_t)(bcol0 + r) * D_MODEL + kof + cc * 8);
    }
}

__global__ __launch_bounds__(256, 2)
void gemm_out(const hf* __restrict__ Ah, const hf* __restrict__ Bh,
              const float* __restrict__ bias, float* __restrict__ Cf)
{
    extern __shared__ char smem[];
    const uint32_t sb = smem_u32(smem);
    const int tid  = threadIdx.x;
    const int lane = tid & 31;
    const int w    = tid >> 5;
    const int wm   = w >> 2;
    const int wn   = w & 3;
    const int brow0 = blockIdx.y * 128;
    const int bcol0 = blockIdx.x * 128;

    if (tid < 128) ((float*)(smem + SM_BIAS))[tid] = bias[bcol0 + tid];

    float c[4][4][4];
    #pragma unroll
    for (int mi = 0; mi < 4; mi++)
        #pragma unroll
        for (int ni = 0; ni < 4; ni++)
            #pragma unroll
            for (int q = 0; q < 4; q++) c[mi][ni][q] = 0.f;

    #pragma unroll
    for (int s = 0; s < GSTAGES - 1; s++) {
        load_stage_AB(sb, Ah, Bh, brow0, bcol0, s, tid);
        cpa_commit();
    }

    const uint32_t a_lrow = a_lane_off(lane, T_ROWB);
    const uint32_t b_lrow = b_lane_off(lane, T_ROWB);

    for (int kt = 0; kt < NCHUNK; kt++) {
        cpa_wait1();
        __syncthreads();
        if (kt + GSTAGES - 1 < NCHUNK)
            load_stage_AB(sb, Ah, Bh, brow0, bcol0, kt + GSTAGES - 1, tid);
        cpa_commit();

        const uint32_t st = sb + (uint32_t)(kt % GSTAGES) * ST_BYTES;
        #pragma unroll
        for (int ks = 0; ks < 2; ks++) {
            const uint32_t kb = ks * 32;
            uint32_t ah[4][4];
            #pragma unroll
            for (int mi = 0; mi < 4; mi++)
                LDSM4(ah[mi], st + OFF_AH
                      + (uint32_t)((wm * 64 + mi * 16) * T_ROWB) + a_lrow + kb);
            uint32_t bh[4][2];
            #pragma unroll
            for (int bi = 0; bi < 2; bi++) {
                uint32_t t4[4];
                LDSM4(t4, st + OFF_BH
                      + (uint32_t)((wn * 32 + bi * 16) * T_ROWB) + b_lrow + kb);
                bh[2 * bi][0] = t4[0]; bh[2 * bi][1] = t4[1];
                bh[2 * bi + 1][0] = t4[2]; bh[2 * bi + 1][1] = t4[3];
            }
            #pragma unroll
            for (int mi = 0; mi < 4; mi++)
                #pragma unroll
                for (int ni = 0; ni < 4; ni++)
                    MMA16816(c[mi][ni], ah[mi], bh[ni]);
        }
    }

    const float* sbias = (const float*)(smem + SM_BIAS);
    const int r0 = lane >> 2;
    const int c0 = (lane & 3) * 2;
    #pragma unroll
    for (int mi = 0; mi < 4; mi++) {
        const int m = brow0 + wm * 64 + mi * 16 + r0;
        #pragma unroll
        for (int ni = 0; ni < 4; ni++) {
            const int n = wn * 32 + ni * 8 + c0;
            const float b0 = sbias[n], b1 = sbias[n + 1];
            *(float2*)(Cf + (size_t)m * D_MODEL + bcol0 + n) =
                make_float2(c[mi][ni][0] + b0, c[mi][ni][1] + b1);
            *(float2*)(Cf + (size_t)(m + 8) * D_MODEL + bcol0 + n) =
                make_float2(c[mi][ni][2] + b0, c[mi][ni][3] + b1);
        }
    }
}

// ---------------- batched weight transpose: W[K,N] -> WT[N,K] fp16 ---------
struct WParams { const float* W[4]; hf* T[4]; };

__global__ void convert_w_all(WParams P)
{
    __shared__ float t[32][33];
    const int z  = blockIdx.z;
    const int bn = blockIdx.x * 32;
    const int bk = blockIdx.y * 32;
    const int tx = threadIdx.x, ty = threadIdx.y;   // (32, 8)
    const float* W = P.W[z];
    hf* TH = P.T[z];
    #pragma unroll
    for (int j = 0; j < 32; j += 8)
        t[ty + j][tx] = W[(size_t)(bk + ty + j) * D_MODEL + bn + tx];
    __syncthreads();
    #pragma unroll
    for (int j = 0; j < 32; j += 8) {
        const size_t o = (size_t)(bn + ty + j) * D_MODEL + bk + tx;
        TH[o] = __float2half_rn(t[tx][ty + j]);
    }
}

// ---------------- zero scratch ---------------------------------------------
__global__ void zero_kernel(float* p, int n)
{
    int i = blockIdx.x * blockDim.x + threadIdx.x;
    if (i < n) p[i] = 0.f;
}

// ---------------- KS[(n,h),d] = sum_s KT[h*64+d][n*4096+s] -----------------
__global__ void ksum_kernel(const hf* __restrict__ KT, float* __restrict__ KS)
{
    __shared__ float red[4];
    const int row = blockIdx.x;
    const int n   = blockIdx.y;
    const int t   = threadIdx.x;
    const float4* p = (const float4*)(KT + (size_t)row * M_TOTAL + n * SEQ);
    float s = 0.f;
    for (int i = t; i < SEQ / 8; i += 128) {
        float4 v = p[i];
        const __half2* h2 = (const __half2*)&v;
        #pragma unroll
        for (int j = 0; j < 4; j++) {
            float2 f = __half22float2(h2[j]);
            s += f.x + f.y;
        }
    }
    #pragma unroll
    for (int o = 16; o > 0; o >>= 1) s += __shfl_down_sync(0xffffffff, s, o);
    if ((t & 31) == 0) red[t >> 5] = s;
    __syncthreads();
    if (t == 0) {
        const int h = row >> 6, d = row & 63;
        KS[((size_t)n * HEADS + h) * HD + d] = red[0] + red[1] + red[2] + red[3];
    }
}

// ---------------- kv_tc: KV[m][d] += sum_s VT[.][s]*KT[.][s] ---------------
#define KVROWB   144
#define KV_TB    (64 * KVROWB)           // 9216
#define KV_ST    (2 * KV_TB)             // 18432
#define KV_SM    (GSTAGES * KV_ST)       // 55296

__device__ __forceinline__ void kv_load_stage(
    uint32_t sb, const hf* __restrict__ Vp, const hf* __restrict__ Kp,
    int kc, int tid)
{
    const uint32_t st = sb + (uint32_t)(kc % GSTAGES) * KV_ST;
    #pragma unroll
    for (int v = 0; v < 2; v++) {
        const int idx = v * 256 + tid;
        const int r  = idx >> 3;
        const int cc = idx & 7;
        const uint32_t so = (uint32_t)(r * KVROWB + cc * 16);
        const size_t g = (size_t)r * M_TOTAL + kc * 64 + cc * 8;
        cp_async16(st + so,         Vp + g);
        cp_async16(st + KV_TB + so, Kp + g);
    }
}

__global__ __launch_bounds__(256, 2)
void kv_tc(const hf* __restrict__ VT, const hf* __restrict__ KT,
           float* __restrict__ KV)
{
    extern __shared__ char smem[];
    const uint32_t sb = smem_u32(smem);
    const int tid  = threadIdx.x;
    const int lane = tid & 31;
    const int w    = tid >> 5;
    const int wm   = w & 3;
    const int wn   = w >> 2;
    const int nh = blockIdx.x;
    const int n  = nh >> 4;
    const int h  = nh & 15;
    const int sp = blockIdx.y;

    const hf* Vp = VT + (size_t)(h * HD) * M_TOTAL + n * SEQ + sp * 512;
    const hf* Kp = KT + (size_t)(h * HD) * M_TOTAL + n * SEQ + sp * 512;

    float c[4][4];
    #pragma unroll
    for (int ni = 0; ni < 4; ni++)
        #pragma unroll
        for (int q = 0; q < 4; q++) c[ni][q] = 0.f;

    #pragma unroll
    for (int s = 0; s < GSTAGES - 1; s++) {
        kv_load_stage(sb, Vp, Kp, s, tid);
        cpa_commit();
    }

    const uint32_t a_lrow = a_lane_off(lane, KVROWB);
    const uint32_t b_lrow = b_lane_off(lane, KVROWB);

    for (int kc = 0; kc < 8; kc++) {
        cpa_wait1();
        __syncthreads();
        if (kc + GSTAGES - 1 < 8)
            kv_load_stage(sb, Vp, Kp, kc + GSTAGES - 1, tid);
        cpa_commit();

        const uint32_t st = sb + (uint32_t)(kc % GSTAGES) * KV_ST;
        #pragma unroll
        for (int ks = 0; ks < 4; ks++) {
            const uint32_t kb = ks * 32;
            uint32_t ah[4];
            LDSM4(ah, st + (uint32_t)(wm * 16 * KVROWB) + a_lrow + kb);
            uint32_t bh[4][2];
            #pragma unroll
            for (int bi = 0; bi < 2; bi++) {
                uint32_t t4[4];
                LDSM4(t4, st + KV_TB + (uint32_t)((wn * 32 + bi * 16) * KVROWB)
                          + b_lrow + kb);
                bh[2 * bi][0] = t4[0]; bh[2 * bi][1] = t4[1];
                bh[2 * bi + 1][0] = t4[2]; bh[2 * bi + 1][1] = t4[3];
            }
            #pragma unroll
            for (int ni = 0; ni < 4; ni++)
                MMA16816(c[ni], ah, bh[ni]);
        }
    }

    const int r0 = lane >> 2;
    const int c0 = (lane & 3) * 2;
    const int m  = wm * 16 + r0;
    #pragma unroll
    for (int ni = 0; ni < 4; ni++) {
        const int d = wn * 32 + ni * 8 + c0;
        float* o = KV + ((size_t)nh * HD + m) * HD + d;
        atomicAdd(o,              c[ni][0]);
        atomicAdd(o + 1,          c[ni][1]);
        atomicAdd(o + 8 * HD,     c[ni][2]);
        atomicAdd(o + 8 * HD + 1, c[ni][3]);
    }
}

// ---------------- KV fp32 -> fp16 ------------------------------------------
__global__ void kvh_kernel(const float* __restrict__ KV, hf* __restrict__ KVh)
{
    int i = blockIdx.x * blockDim.x + threadIdx.x;
    float4 v = ((const float4*)KV)[i];
    ((__half2*)KVh)[2 * i]     = __floats2half2_rn(v.x, v.y);
    ((__half2*)KVh)[2 * i + 1] = __floats2half2_rn(v.z, v.w);
}

// ---------------- attn_out_tc ----------------------------------------------
__global__ __launch_bounds__(256)
void attn_out_tc(const hf* __restrict__ Qh, const hf* __restrict__ KVh,
                 const float* __restrict__ KS, hf* __restrict__ Out)
{
    __shared__ hf Qs[128 * 72];
    __shared__ hf Bs[64 * 72];
    __shared__ float ks[64];
    __shared__ float zs[128];

    const int tid  = threadIdx.x;
    const int lane = tid & 31;
    const int w    = tid >> 5;
    const int wm   = w >> 1;
    const int wn   = w & 1;
    const int nh = blockIdx.y;
    const int n  = nh >> 4;
    const int h  = nh & 15;
    const int l0 = blockIdx.x * 128;

    const uint32_t sq = smem_u32(Qs);
    const uint32_t sbv = smem_u32(Bs);

    #pragma unroll
    for (int v = 0; v < 4; v++) {
        const int idx = v * 256 + tid;
        const int r = idx >> 3, cc = idx & 7;
        cp_async16(sq + (uint32_t)(r * 144 + cc * 16),
                   Qh + (size_t)(n * SEQ + l0 + r) * D_MODEL + h * HD + cc * 8);
    }
    #pragma unroll
    for (int v = 0; v < 2; v++) {
        const int idx = v * 256 + tid;
        const int r = idx >> 3, cc = idx & 7;
        cp_async16(sbv + (uint32_t)(r * 144 + cc * 16),
                   KVh + ((size_t)nh * HD + r) * HD + cc * 8);
    }
    if (tid < 64) ks[tid] = KS[(size_t)nh * HD + tid];
    cpa_commit();
    cpa_wait0();
    __syncthreads();

    if (tid < 128) {
        float a = 0.f;
        #pragma unroll 8
        for (int d = 0; d < 64; d++)
            a += __half2float(Qs[tid * 72 + d]) * ks[d];
        zs[tid] = 1.f / (a + 1e-10f);
    }
    __syncthreads();

    const uint32_t a_lrow = a_lane_off(lane, 144);
    const uint32_t b_lrow = b_lane_off(lane, 144);

    float c[2][4][4];
    #pragma unroll
    for (int mi = 0; mi < 2; mi++)
        #pragma unroll
        for (int ni = 0; ni < 4; ni++)
            #pragma unroll
            for (int q = 0; q < 4; q++) c[mi][ni][q] = 0.f;

    #pragma unroll
    for (int ks_ = 0; ks_ < 4; ks_++) {
        const uint32_t kb = ks_ * 32;
        uint32_t ah[2][4];
        #pragma unroll
        for (int mi = 0; mi < 2; mi++)
            LDSM4(ah[mi], sq + (uint32_t)((wm * 32 + mi * 16) * 144) + a_lrow + kb);
        uint32_t bh[4][2];
        #pragma unroll
        for (int bi = 0; bi < 2; bi++) {
            uint32_t t4[4];
            LDSM4(t4, sbv + (uint32_t)((wn * 32 + bi * 16) * 144) + b_lrow + kb);
            bh[2 * bi][0] = t4[0]; bh[2 * bi][1] = t4[1];
            bh[2 * bi + 1][0] = t4[2]; bh[2 * bi + 1][1] = t4[3];
        }
        #pragma unroll
        for (int mi = 0; mi < 2; mi++)
            #pragma unroll
            for (int ni = 0; ni < 4; ni++)
                MMA16816(c[mi][ni], ah[mi], bh[ni]);
    }

    const int r0 = lane >> 2;
    const int c0 = (lane & 3) * 2;
    #pragma unroll
    for (int mi = 0; mi < 2; mi++) {
        const int lloc = wm * 32 + mi * 16 + r0;
        const float z0 = zs[lloc];
        const float z1 = zs[lloc + 8];
        #pragma unroll
        for (int ni = 0; ni < 4; ni++) {
            const int m = wn * 32 + ni * 8 + c0;
            hf* o = Out + (size_t)(n * SEQ + l0 + lloc) * D_MODEL + h * HD + m;
            *(__half2*)o = __floats2half2_rn(c[mi][ni][0] * z0, c[mi][ni][1] * z0);
            *(__half2*)(o + 8 * D_MODEL) =
                __floats2half2_rn(c[mi][ni][2] * z1, c[mi][ni][3] * z1);
        }
    }
}

// ---------------- launch ---------------------------------------------------
extern "C" void kernel_launch(void* const* d_in, const int* in_sizes, int n_in,
                              void* d_out, int out_size)
{
    const float* queries = (const float*)d_in[0];
    const float* keys    = (const float*)d_in[1];
    const float* values  = (const float*)d_in[2];
    const float* Wq = (const float*)d_in[3];
    const float* bq = (const float*)d_in[4];
    const float* Wk = (const float*)d_in[5];
    const float* bk = (const float*)d_in[6];
    const float* Wv = (const float*)d_in[7];
    const float* bv = (const float*)d_in[8];
    const float* Wo = (const float*)d_in[9];
    const float* bo = (const float*)d_in[10];
    float* out = (float*)d_out;

    void *pKV, *pKVh, *pKS, *pAh, *pQh, *pKT, *pVT;
    void *pWqh, *pWkh, *pWvh, *pWoh;
    cudaGetSymbolAddress(&pKV,  g_KV);
    cudaGetSymbolAddress(&pKVh, g_KVh);
    cudaGetSymbolAddress(&pKS,  g_KS);
    cudaGetSymbolAddress(&pAh,  g_Ah);
    cudaGetSymbolAddress(&pQh,  g_Qh);
    cudaGetSymbolAddress(&pKT,  g_KT);
    cudaGetSymbolAddress(&pVT,  g_VT);
    cudaGetSymbolAddress(&pWqh, g_Wqh);
    cudaGetSymbolAddress(&pWkh, g_Wkh);
    cudaGetSymbolAddress(&pWvh, g_Wvh);
    cudaGetSymbolAddress(&pWoh, g_Woh);

    cudaFuncSetAttribute(gemm_proj, cudaFuncAttributeMaxDynamicSharedMemorySize, SM_TOTAL);
    cudaFuncSetAttribute(gemm_out,  cudaFuncAttributeMaxDynamicSharedMemorySize, SM_TOTAL);
    cudaFuncSetAttribute(kv_tc,     cudaFuncAttributeMaxDynamicSharedMemorySize, KV_SM);

    // batched weight transpose
    WParams wp;
    wp.W[0] = Wq; wp.T[0] = (hf*)pWqh;
    wp.W[1] = Wk; wp.T[1] = (hf*)pWkh;
    wp.W[2] = Wv; wp.T[2] = (hf*)pWvh;
    wp.W[3] = Wo; wp.T[3] = (hf*)pWoh;
    convert_w_all<<<dim3(32, 32, 4), dim3(32, 8)>>>(wp);

    zero_kernel<<<(NH * HD * HD + 255) / 256, 256>>>((float*)pKV, NH * HD * HD);

    // batched Q/K/V projections (A converted in-kernel; 1 CTA/SM, no spills)
    ProjParams pp;
    pp.A[0] = queries; pp.W[0] = (hf*)pWqh; pp.bias[0] = bq; pp.out[0] = (hf*)pQh;
    pp.A[1] = keys;    pp.W[1] = (hf*)pWkh; pp.bias[1] = bk; pp.out[1] = (hf*)pKT;
    pp.A[2] = values;  pp.W[2] = (hf*)pWvh; pp.bias[2] = bv; pp.out[2] = (hf*)pVT;
    gemm_proj<<<dim3(8, 128, 3), 256, SM_TOTAL>>>(pp);

    // attention core (tensor-core)
    ksum_kernel<<<dim3(D_MODEL, N_BATCH), 128>>>((const hf*)pKT, (float*)pKS);
    kv_tc<<<dim3(NH, 8), 256, KV_SM>>>((const hf*)pVT, (const hf*)pKT, (float*)pKV);
    kvh_kernel<<<NH * HD * HD / 1024, 256>>>((const float*)pKV, (hf*)pKVh);
    attn_out_tc<<<dim3(SEQ / 128, NH), 256>>>((const hf*)pQh, (const hf*)pKVh,
                                              (const float*)pKS, (hf*)pAh);

    // output projection
    gemm_out<<<dim3(8, 128), 256, SM_TOTAL>>>((const hf*)pAh, (const hf*)pWoh, bo, out);
}

// round 17
// speedup vs baseline: 1.2821x; 1.2821x over previous
#include <cuda_runtime.h>
#include <cuda_fp16.h>
#include <math.h>
#include <cstdint>

// Problem constants
#define D_MODEL 1024
#define N_BATCH 4
#define SEQ     4096
#define HEADS   16
#define HD      64
#define NH      (N_BATCH * HEADS)        // 64
#define M_TOTAL (N_BATCH * SEQ)          // 16384

typedef unsigned long long ull;
typedef __half hf;

// ---------------- scratch (device globals: no allocation allowed) ----------
__device__ float g_KV [NH * HD * HD];       // per-(n,h) KV[m][d] fp32 accum
__device__ hf    g_KVh[NH * HD * HD];       // fp16 copy for MMA
__device__ float g_KS [NH * HD];            // per-(n,h) K_sum[d]

__device__ hf g_Ah[M_TOTAL * D_MODEL];      // fp16 queries; later attn output
__device__ hf g_A1[M_TOTAL * D_MODEL];      // fp16 keys
__device__ hf g_A2[M_TOTAL * D_MODEL];      // fp16 values
__device__ hf g_Qh[M_TOTAL * D_MODEL];      // Q_lin fp16 [token][channel]
__device__ hf g_KT[D_MODEL * M_TOTAL];      // K_lin^T fp16 [channel][token]
__device__ hf g_VT[D_MODEL * M_TOTAL];      // V^T     fp16 [channel][token]
__device__ hf g_Wqh[D_MODEL * D_MODEL];
__device__ hf g_Wkh[D_MODEL * D_MODEL];
__device__ hf g_Wvh[D_MODEL * D_MODEL];
__device__ hf g_Woh[D_MODEL * D_MODEL];

// ---------------- ptx helpers ---------------------------------------------
__device__ __forceinline__ uint32_t smem_u32(const void* p) {
    uint32_t a;
    asm("{ .reg .u64 t; cvta.to.shared.u64 t, %1; cvt.u32.u64 %0, t; }" : "=r"(a) : "l"(p));
    return a;
}
__device__ __forceinline__ void cp_async16(uint32_t s, const void* g) {
    asm volatile("cp.async.cg.shared.global [%0], [%1], 16;" :: "r"(s), "l"(g));
}
__device__ __forceinline__ void cpa_commit() { asm volatile("cp.async.commit_group;" ::: "memory"); }
__device__ __forceinline__ void cpa_wait1()  { asm volatile("cp.async.wait_group 1;" ::: "memory"); }
__device__ __forceinline__ void cpa_wait0()  { asm volatile("cp.async.wait_group 0;" ::: "memory"); }

#define LDSM4(r, a) \
    asm volatile("ldmatrix.sync.aligned.m8n8.x4.shared.b16 {%0,%1,%2,%3}, [%4];" \
        : "=r"((r)[0]), "=r"((r)[1]), "=r"((r)[2]), "=r"((r)[3]) : "r"(a))

#define MMA16816(d, a, b) \
    asm volatile("mma.sync.aligned.m16n8k16.row.col.f32.f16.f16.f32 " \
        "{%0,%1,%2,%3}, {%4,%5,%6,%7}, {%8,%9}, {%0,%1,%2,%3};" \
        : "+f"((d)[0]), "+f"((d)[1]), "+f"((d)[2]), "+f"((d)[3]) \
        : "r"((a)[0]), "r"((a)[1]), "r"((a)[2]), "r"((a)[3]), \
          "r"((b)[0]), "r"((b)[1]))

// ldmatrix lane-offset generators (validated R5-R12), parametric in row stride
__device__ __forceinline__ uint32_t a_lane_off(int lane, int rowb) {
    return (uint32_t)((lane & 15) * rowb + ((lane >> 4) << 4));
}
__device__ __forceinline__ uint32_t b_lane_off(int lane, int rowb) {
    return (uint32_t)(((((lane >> 4) & 1) * 8 + (lane & 7)) * rowb)
                      + (((lane >> 3) & 1) << 4));
}

// ================= GEMM tiling constants ===================================
#define T_ROWB   80
#define T_BYTES  (128 * T_ROWB)          // 10240
#define ST_BYTES (2 * T_BYTES)           // 20480
#define OFF_AH   0
#define OFF_BH   T_BYTES
#define GSTAGES  3
#define SM_BIAS  (GSTAGES * ST_BYTES)    // 61440
#define SM_TOTAL (SM_BIAS + 512)
#define NCHUNK   (D_MODEL / 32)          // 32
#define TR_STRIDE 136                    // transpose buffer halves/row

// ---------------- A+B cp.async staging (R11-proven) -------------------------
__device__ __forceinline__ void load_stage_AB(
    uint32_t sb, const hf* __restrict__ Ah, const hf* __restrict__ Bh,
    int brow0, int bcol0, int kt, int tid)
{
    const uint32_t st = sb + (uint32_t)(kt % GSTAGES) * ST_BYTES;
    const size_t kof = (size_t)kt * 32;
    #pragma unroll
    for (int v = 0; v < 2; v++) {
        const int idx = v * 256 + tid;
        const int r  = idx >> 2;
        const int cc = idx & 3;
        const uint32_t so = (uint32_t)(r * T_ROWB + cc * 16);
        cp_async16(st + OFF_AH + so, Ah + (size_t)(brow0 + r) * D_MODEL + kof + cc * 8);
        cp_async16(st + OFF_BH + so, Bh + (size_t)(bcol0 + r) * D_MODEL + kof + cc * 8);
    }
}

// ================= batched projection GEMM (z = Q/K/V) =====================
// C[M,1024] = elu?(A_h[M,1024] * W^T + bias); output fp16 normal (z=0)
// or fp16 transposed [channel][token] (z=1,2). A is pre-converted fp16
// loaded via cp.async — identical mainloop to the 561us R11 gemm_tc, (256,2).
struct ProjParams {
    const hf*    A[3];
    const hf*    W[3];
    const float* bias[3];
    hf*          out[3];
};

__global__ __launch_bounds__(256, 2)
void gemm_proj(ProjParams P)
{
    extern __shared__ char smem[];
    const uint32_t sb = smem_u32(smem);
    const int tid  = threadIdx.x;
    const int lane = tid & 31;
    const int w    = tid >> 5;
    const int wm   = w >> 2;
    const int wn   = w & 3;
    const int z    = blockIdx.z;
    const int brow0 = blockIdx.y * 128;
    const int bcol0 = blockIdx.x * 128;

    const hf* Ah = P.A[z];
    const hf* Bh = P.W[z];

    if (tid < 128) ((float*)(smem + SM_BIAS))[tid] = P.bias[z][bcol0 + tid];

    float c[4][4][4];
    #pragma unroll
    for (int mi = 0; mi < 4; mi++)
        #pragma unroll
        for (int ni = 0; ni < 4; ni++)
            #pragma unroll
            for (int q = 0; q < 4; q++) c[mi][ni][q] = 0.f;

    #pragma unroll
    for (int s = 0; s < GSTAGES - 1; s++) {
        load_stage_AB(sb, Ah, Bh, brow0, bcol0, s, tid);
        cpa_commit();
    }

    const uint32_t a_lrow = a_lane_off(lane, T_ROWB);
    const uint32_t b_lrow = b_lane_off(lane, T_ROWB);

    for (int kt = 0; kt < NCHUNK; kt++) {
        cpa_wait1();
        __syncthreads();
        if (kt + GSTAGES - 1 < NCHUNK)
            load_stage_AB(sb, Ah, Bh, brow0, bcol0, kt + GSTAGES - 1, tid);
        cpa_commit();

        const uint32_t st = sb + (uint32_t)(kt % GSTAGES) * ST_BYTES;
        #pragma unroll
        for (int ks = 0; ks < 2; ks++) {
            const uint32_t kb = ks * 32;
            uint32_t ah[4][4];
            #pragma unroll
            for (int mi = 0; mi < 4; mi++)
                LDSM4(ah[mi], st + OFF_AH
                      + (uint32_t)((wm * 64 + mi * 16) * T_ROWB) + a_lrow + kb);
            uint32_t bh[4][2];
            #pragma unroll
            for (int bi = 0; bi < 2; bi++) {
                uint32_t t4[4];
                LDSM4(t4, st + OFF_BH
                      + (uint32_t)((wn * 32 + bi * 16) * T_ROWB) + b_lrow + kb);
                bh[2 * bi][0] = t4[0]; bh[2 * bi][1] = t4[1];
                bh[2 * bi + 1][0] = t4[2]; bh[2 * bi + 1][1] = t4[3];
            }
            #pragma unroll
            for (int mi = 0; mi < 4; mi++)
                #pragma unroll
                for (int ni = 0; ni < 4; ni++)
                    MMA16816(c[mi][ni], ah[mi], bh[ni]);
        }
    }

    // ---------------- epilogue ----------------
    const float* sbias = (const float*)(smem + SM_BIAS);
    const int r0 = lane >> 2;
    const int c0 = (lane & 3) * 2;
    const int act = (z <= 1);
    hf* Ch = P.out[z];

    if (z != 0) {
        // transposed fp16 output [channel][token]
        __syncthreads();
        hf* TR = (hf*)smem;
        #pragma unroll
        for (int mi = 0; mi < 4; mi++) {
            const int m0 = wm * 64 + mi * 16 + r0;
            #pragma unroll
            for (int ni = 0; ni < 4; ni++) {
                const int n = wn * 32 + ni * 8 + c0;
                const float b0 = sbias[n], b1 = sbias[n + 1];
                float v0 = c[mi][ni][0] + b0;
                float v1 = c[mi][ni][1] + b1;
                float v2 = c[mi][ni][2] + b0;
                float v3 = c[mi][ni][3] + b1;
                if (act) {
                    v0 = (v0 > 0.f) ? (v0 + 1.f) : expf(v0);
                    v1 = (v1 > 0.f) ? (v1 + 1.f) : expf(v1);
                    v2 = (v2 > 0.f) ? (v2 + 1.f) : expf(v2);
                    v3 = (v3 > 0.f) ? (v3 + 1.f) : expf(v3);
                }
                TR[n * TR_STRIDE + m0]           = __float2half_rn(v0);
                TR[(n + 1) * TR_STRIDE + m0]     = __float2half_rn(v1);
                TR[n * TR_STRIDE + m0 + 8]       = __float2half_rn(v2);
                TR[(n + 1) * TR_STRIDE + m0 + 8] = __float2half_rn(v3);
            }
        }
        __syncthreads();
        for (int i = tid; i < 128 * 16; i += 256) {
            const int n = i >> 4, seg = i & 15;
            float4 val = *(float4*)&TR[n * TR_STRIDE + seg * 8];
            *(float4*)(Ch + (size_t)(bcol0 + n) * M_TOTAL + brow0 + seg * 8) = val;
        }
        return;
    }

    // normal fp16 output (Q_lin)
    #pragma unroll
    for (int mi = 0; mi < 4; mi++) {
        const int m = brow0 + wm * 64 + mi * 16 + r0;
        #pragma unroll
        for (int ni = 0; ni < 4; ni++) {
            const int n = wn * 32 + ni * 8 + c0;
            const float b0 = sbias[n], b1 = sbias[n + 1];
            float v0 = c[mi][ni][0] + b0;
            float v1 = c[mi][ni][1] + b1;
            float v2 = c[mi][ni][2] + b0;
            float v3 = c[mi][ni][3] + b1;
            v0 = (v0 > 0.f) ? (v0 + 1.f) : expf(v0);
            v1 = (v1 > 0.f) ? (v1 + 1.f) : expf(v1);
            v2 = (v2 > 0.f) ? (v2 + 1.f) : expf(v2);
            v3 = (v3 > 0.f) ? (v3 + 1.f) : expf(v3);
            *(__half2*)(Ch + (size_t)m * D_MODEL + bcol0 + n)       = __floats2half2_rn(v0, v1);
            *(__half2*)(Ch + (size_t)(m + 8) * D_MODEL + bcol0 + n) = __floats2half2_rn(v2, v3);
        }
    }
}

// ================= output GEMM (fp16 A via cp.async, fp32 out) =============
__global__ __launch_bounds__(256, 2)
void gemm_out(const hf* __restrict__ Ah, const hf* __restrict__ Bh,
              const float* __restrict__ bias, float* __restrict__ Cf)
{
    extern __shared__ char smem[];
    const uint32_t sb = smem_u32(smem);
    const int tid  = threadIdx.x;
    const int lane = tid & 31;
    const int w    = tid >> 5;
    const int wm   = w >> 2;
    const int wn   = w & 3;
    const int brow0 = blockIdx.y * 128;
    const int bcol0 = blockIdx.x * 128;

    if (tid < 128) ((float*)(smem + SM_BIAS))[tid] = bias[bcol0 + tid];

    float c[4][4][4];
    #pragma unroll
    for (int mi = 0; mi < 4; mi++)
        #pragma unroll
        for (int ni = 0; ni < 4; ni++)
            #pragma unroll
            for (int q = 0; q < 4; q++) c[mi][ni][q] = 0.f;

    #pragma unroll
    for (int s = 0; s < GSTAGES - 1; s++) {
        load_stage_AB(sb, Ah, Bh, brow0, bcol0, s, tid);
        cpa_commit();
    }

    const uint32_t a_lrow = a_lane_off(lane, T_ROWB);
    const uint32_t b_lrow = b_lane_off(lane, T_ROWB);

    for (int kt = 0; kt < NCHUNK; kt++) {
        cpa_wait1();
        __syncthreads();
        if (kt + GSTAGES - 1 < NCHUNK)
            load_stage_AB(sb, Ah, Bh, brow0, bcol0, kt + GSTAGES - 1, tid);
        cpa_commit();

        const uint32_t st = sb + (uint32_t)(kt % GSTAGES) * ST_BYTES;
        #pragma unroll
        for (int ks = 0; ks < 2; ks++) {
            const uint32_t kb = ks * 32;
            uint32_t ah[4][4];
            #pragma unroll
            for (int mi = 0; mi < 4; mi++)
                LDSM4(ah[mi], st + OFF_AH
                      + (uint32_t)((wm * 64 + mi * 16) * T_ROWB) + a_lrow + kb);
            uint32_t bh[4][2];
            #pragma unroll
            for (int bi = 0; bi < 2; bi++) {
                uint32_t t4[4];
                LDSM4(t4, st + OFF_BH
                      + (uint32_t)((wn * 32 + bi * 16) * T_ROWB) + b_lrow + kb);
                bh[2 * bi][0] = t4[0]; bh[2 * bi][1] = t4[1];
                bh[2 * bi + 1][0] = t4[2]; bh[2 * bi + 1][1] = t4[3];
            }
            #pragma unroll
            for (int mi = 0; mi < 4; mi++)
                #pragma unroll
                for (int ni = 0; ni < 4; ni++)
                    MMA16816(c[mi][ni], ah[mi], bh[ni]);
        }
    }

    const float* sbias = (const float*)(smem + SM_BIAS);
    const int r0 = lane >> 2;
    const int c0 = (lane & 3) * 2;
    #pragma unroll
    for (int mi = 0; mi < 4; mi++) {
        const int m = brow0 + wm * 64 + mi * 16 + r0;
        #pragma unroll
        for (int ni = 0; ni < 4; ni++) {
            const int n = wn * 32 + ni * 8 + c0;
            const float b0 = sbias[n], b1 = sbias[n + 1];
            *(float2*)(Cf + (size_t)m * D_MODEL + bcol0 + n) =
                make_float2(c[mi][ni][0] + b0, c[mi][ni][1] + b1);
            *(float2*)(Cf + (size_t)(m + 8) * D_MODEL + bcol0 + n) =
                make_float2(c[mi][ni][2] + b0, c[mi][ni][3] + b1);
        }
    }
}

// ---------------- batched fp32 -> fp16 conversion (z = Q/K/V inputs) -------
struct AParams { const float* X[3]; hf* H[3]; };

__global__ void convert_a_all(AParams P)
{
    const int z = blockIdx.z;
    const float* X = P.X[z];
    hf* H = P.H[z];
    int i = blockIdx.x * blockDim.x + threadIdx.x;
    float4 x = ((const float4*)X)[i];
    ((__half2*)H)[2 * i]     = __floats2half2_rn(x.x, x.y);
    ((__half2*)H)[2 * i + 1] = __floats2half2_rn(x.z, x.w);
}

// ---------------- batched weight transpose: W[K,N] -> WT[N,K] fp16 ---------
struct WParams { const float* W[4]; hf* T[4]; };

__global__ void convert_w_all(WParams P)
{
    __shared__ float t[32][33];
    const int z  = blockIdx.z;
    const int bn = blockIdx.x * 32;
    const int bk = blockIdx.y * 32;
    const int tx = threadIdx.x, ty = threadIdx.y;   // (32, 8)
    const float* W = P.W[z];
    hf* TH = P.T[z];
    #pragma unroll
    for (int j = 0; j < 32; j += 8)
        t[ty + j][tx] = W[(size_t)(bk + ty + j) * D_MODEL + bn + tx];
    __syncthreads();
    #pragma unroll
    for (int j = 0; j < 32; j += 8) {
        const size_t o = (size_t)(bn + ty + j) * D_MODEL + bk + tx;
        TH[o] = __float2half_rn(t[tx][ty + j]);
    }
}

// ---------------- zero scratch ---------------------------------------------
__global__ void zero_kernel(float* p, int n)
{
    int i = blockIdx.x * blockDim.x + threadIdx.x;
    if (i < n) p[i] = 0.f;
}

// ---------------- KS[(n,h),d] = sum_s KT[h*64+d][n*4096+s] -----------------
__global__ void ksum_kernel(const hf* __restrict__ KT, float* __restrict__ KS)
{
    __shared__ float red[4];
    const int row = blockIdx.x;
    const int n   = blockIdx.y;
    const int t   = threadIdx.x;
    const float4* p = (const float4*)(KT + (size_t)row * M_TOTAL + n * SEQ);
    float s = 0.f;
    for (int i = t; i < SEQ / 8; i += 128) {
        float4 v = p[i];
        const __half2* h2 = (const __half2*)&v;
        #pragma unroll
        for (int j = 0; j < 4; j++) {
            float2 f = __half22float2(h2[j]);
            s += f.x + f.y;
        }
    }
    #pragma unroll
    for (int o = 16; o > 0; o >>= 1) s += __shfl_down_sync(0xffffffff, s, o);
    if ((t & 31) == 0) red[t >> 5] = s;
    __syncthreads();
    if (t == 0) {
        const int h = row >> 6, d = row & 63;
        KS[((size_t)n * HEADS + h) * HD + d] = red[0] + red[1] + red[2] + red[3];
    }
}

// ---------------- kv_tc: KV[m][d] += sum_s VT[.][s]*KT[.][s] ---------------
#define KVROWB   144
#define KV_TB    (64 * KVROWB)           // 9216
#define KV_ST    (2 * KV_TB)             // 18432
#define KV_SM    (GSTAGES * KV_ST)       // 55296

__device__ __forceinline__ void kv_load_stage(
    uint32_t sb, const hf* __restrict__ Vp, const hf* __restrict__ Kp,
    int kc, int tid)
{
    const uint32_t st = sb + (uint32_t)(kc % GSTAGES) * KV_ST;
    #pragma unroll
    for (int v = 0; v < 2; v++) {
        const int idx = v * 256 + tid;
        const int r  = idx >> 3;
        const int cc = idx & 7;
        const uint32_t so = (uint32_t)(r * KVROWB + cc * 16);
        const size_t g = (size_t)r * M_TOTAL + kc * 64 + cc * 8;
        cp_async16(st + so,         Vp + g);
        cp_async16(st + KV_TB + so, Kp + g);
    }
}

__global__ __launch_bounds__(256, 2)
void kv_tc(const hf* __restrict__ VT, const hf* __restrict__ KT,
           float* __restrict__ KV)
{
    extern __shared__ char smem[];
    const uint32_t sb = smem_u32(smem);
    const int tid  = threadIdx.x;
    const int lane = tid & 31;
    const int w    = tid >> 5;
    const int wm   = w & 3;
    const int wn   = w >> 2;
    const int nh = blockIdx.x;
    const int n  = nh >> 4;
    const int h  = nh & 15;
    const int sp = blockIdx.y;

    const hf* Vp = VT + (size_t)(h * HD) * M_TOTAL + n * SEQ + sp * 512;
    const hf* Kp = KT + (size_t)(h * HD) * M_TOTAL + n * SEQ + sp * 512;

    float c[4][4];
    #pragma unroll
    for (int ni = 0; ni < 4; ni++)
        #pragma unroll
        for (int q = 0; q < 4; q++) c[ni][q] = 0.f;

    #pragma unroll
    for (int s = 0; s < GSTAGES - 1; s++) {
        kv_load_stage(sb, Vp, Kp, s, tid);
        cpa_commit();
    }

    const uint32_t a_lrow = a_lane_off(lane, KVROWB);
    const uint32_t b_lrow = b_lane_off(lane, KVROWB);

    for (int kc = 0; kc < 8; kc++) {
        cpa_wait1();
        __syncthreads();
        if (kc + GSTAGES - 1 < 8)
            kv_load_stage(sb, Vp, Kp, kc + GSTAGES - 1, tid);
        cpa_commit();

        const uint32_t st = sb + (uint32_t)(kc % GSTAGES) * KV_ST;
        #pragma unroll
        for (int ks = 0; ks < 4; ks++) {
            const uint32_t kb = ks * 32;
            uint32_t ah[4];
            LDSM4(ah, st + (uint32_t)(wm * 16 * KVROWB) + a_lrow + kb);
            uint32_t bh[4][2];
            #pragma unroll
            for (int bi = 0; bi < 2; bi++) {
                uint32_t t4[4];
                LDSM4(t4, st + KV_TB + (uint32_t)((wn * 32 + bi * 16) * KVROWB)
                          + b_lrow + kb);
                bh[2 * bi][0] = t4[0]; bh[2 * bi][1] = t4[1];
                bh[2 * bi + 1][0] = t4[2]; bh[2 * bi + 1][1] = t4[3];
            }
            #pragma unroll
            for (int ni = 0; ni < 4; ni++)
                MMA16816(c[ni], ah, bh[ni]);
        }
    }

    const int r0 = lane >> 2;
    const int c0 = (lane & 3) * 2;
    const int m  = wm * 16 + r0;
    #pragma unroll
    for (int ni = 0; ni < 4; ni++) {
        const int d = wn * 32 + ni * 8 + c0;
        float* o = KV + ((size_t)nh * HD + m) * HD + d;
        atomicAdd(o,              c[ni][0]);
        atomicAdd(o + 1,          c[ni][1]);
        atomicAdd(o + 8 * HD,     c[ni][2]);
        atomicAdd(o + 8 * HD + 1, c[ni][3]);
    }
}

// ---------------- KV fp32 -> fp16 ------------------------------------------
__global__ void kvh_kernel(const float* __restrict__ KV, hf* __restrict__ KVh)
{
    int i = blockIdx.x * blockDim.x + threadIdx.x;
    float4 v = ((const float4*)KV)[i];
    ((__half2*)KVh)[2 * i]     = __floats2half2_rn(v.x, v.y);
    ((__half2*)KVh)[2 * i + 1] = __floats2half2_rn(v.z, v.w);
}

// ---------------- attn_out_tc ----------------------------------------------
__global__ __launch_bounds__(256)
void attn_out_tc(const hf* __restrict__ Qh, const hf* __restrict__ KVh,
                 const float* __restrict__ KS, hf* __restrict__ Out)
{
    __shared__ hf Qs[128 * 72];
    __shared__ hf Bs[64 * 72];
    __shared__ float ks[64];
    __shared__ float zs[128];

    const int tid  = threadIdx.x;
    const int lane = tid & 31;
    const int w    = tid >> 5;
    const int wm   = w >> 1;
    const int wn   = w & 1;
    const int nh = blockIdx.y;
    const int n  = nh >> 4;
    const int h  = nh & 15;
    const int l0 = blockIdx.x * 128;

    const uint32_t sq = smem_u32(Qs);
    const uint32_t sbv = smem_u32(Bs);

    #pragma unroll
    for (int v = 0; v < 4; v++) {
        const int idx = v * 256 + tid;
        const int r = idx >> 3, cc = idx & 7;
        cp_async16(sq + (uint32_t)(r * 144 + cc * 16),
                   Qh + (size_t)(n * SEQ + l0 + r) * D_MODEL + h * HD + cc * 8);
    }
    #pragma unroll
    for (int v = 0; v < 2; v++) {
        const int idx = v * 256 + tid;
        const int r = idx >> 3, cc = idx & 7;
        cp_async16(sbv + (uint32_t)(r * 144 + cc * 16),
                   KVh + ((size_t)nh * HD + r) * HD + cc * 8);
    }
    if (tid < 64) ks[tid] = KS[(size_t)nh * HD + tid];
    cpa_commit();
    cpa_wait0();
    __syncthreads();

    if (tid < 128) {
        float a = 0.f;
        #pragma unroll 8
        for (int d = 0; d < 64; d++)
            a += __half2float(Qs[tid * 72 + d]) * ks[d];
        zs[tid] = 1.f / (a + 1e-10f);
    }
    __syncthreads();

    const uint32_t a_lrow = a_lane_off(lane, 144);
    const uint32_t b_lrow = b_lane_off(lane, 144);

    float c[2][4][4];
    #pragma unroll
    for (int mi = 0; mi < 2; mi++)
        #pragma unroll
        for (int ni = 0; ni < 4; ni++)
            #pragma unroll
            for (int q = 0; q < 4; q++) c[mi][ni][q] = 0.f;

    #pragma unroll
    for (int ks_ = 0; ks_ < 4; ks_++) {
        const uint32_t kb = ks_ * 32;
        uint32_t ah[2][4];
        #pragma unroll
        for (int mi = 0; mi < 2; mi++)
            LDSM4(ah[mi], sq + (uint32_t)((wm * 32 + mi * 16) * 144) + a_lrow + kb);
        uint32_t bh[4][2];
        #pragma unroll
        for (int bi = 0; bi < 2; bi++) {
            uint32_t t4[4];
            LDSM4(t4, sbv + (uint32_t)((wn * 32 + bi * 16) * 144) + b_lrow + kb);
            bh[2 * bi][0] = t4[0]; bh[2 * bi][1] = t4[1];
            bh[2 * bi + 1][0] = t4[2]; bh[2 * bi + 1][1] = t4[3];
        }
        #pragma unroll
        for (int mi = 0; mi < 2; mi++)
            #pragma unroll
            for (int ni = 0; ni < 4; ni++)
                MMA16816(c[mi][ni], ah[mi], bh[ni]);
    }

    const int r0 = lane >> 2;
    const int c0 = (lane & 3) * 2;
    #pragma unroll
    for (int mi = 0; mi < 2; mi++) {
        const int lloc = wm * 32 + mi * 16 + r0;
        const float z0 = zs[lloc];
        const float z1 = zs[lloc + 8];
        #pragma unroll
        for (int ni = 0; ni < 4; ni++) {
            const int m = wn * 32 + ni * 8 + c0;
            hf* o = Out + (size_t)(n * SEQ + l0 + lloc) * D_MODEL + h * HD + m;
            *(__half2*)o = __floats2half2_rn(c[mi][ni][0] * z0, c[mi][ni][1] * z0);
            *(__half2*)(o + 8 * D_MODEL) =
                __floats2half2_rn(c[mi][ni][2] * z1, c[mi][ni][3] * z1);
        }
    }
}

// ---------------- launch ---------------------------------------------------
extern "C" void kernel_launch(void* const* d_in, const int* in_sizes, int n_in,
                              void* d_out, int out_size)
{
    const float* queries = (const float*)d_in[0];
    const float* keys    = (const float*)d_in[1];
    const float* values  = (const float*)d_in[2];
    const float* Wq = (const float*)d_in[3];
    const float* bq = (const float*)d_in[4];
    const float* Wk = (const float*)d_in[5];
    const float* bk = (const float*)d_in[6];
    const float* Wv = (const float*)d_in[7];
    const float* bv = (const float*)d_in[8];
    const float* Wo = (const float*)d_in[9];
    const float* bo = (const float*)d_in[10];
    float* out = (float*)d_out;

    void *pKV, *pKVh, *pKS, *pAh, *pA1, *pA2, *pQh, *pKT, *pVT;
    void *pWqh, *pWkh, *pWvh, *pWoh;
    cudaGetSymbolAddress(&pKV,  g_KV);
    cudaGetSymbolAddress(&pKVh, g_KVh);
    cudaGetSymbolAddress(&pKS,  g_KS);
    cudaGetSymbolAddress(&pAh,  g_Ah);
    cudaGetSymbolAddress(&pA1,  g_A1);
    cudaGetSymbolAddress(&pA2,  g_A2);
    cudaGetSymbolAddress(&pQh,  g_Qh);
    cudaGetSymbolAddress(&pKT,  g_KT);
    cudaGetSymbolAddress(&pVT,  g_VT);
    cudaGetSymbolAddress(&pWqh, g_Wqh);
    cudaGetSymbolAddress(&pWkh, g_Wkh);
    cudaGetSymbolAddress(&pWvh, g_Wvh);
    cudaGetSymbolAddress(&pWoh, g_Woh);

    cudaFuncSetAttribute(gemm_proj, cudaFuncAttributeMaxDynamicSharedMemorySize, SM_TOTAL);
    cudaFuncSetAttribute(gemm_out,  cudaFuncAttributeMaxDynamicSharedMemorySize, SM_TOTAL);
    cudaFuncSetAttribute(kv_tc,     cudaFuncAttributeMaxDynamicSharedMemorySize, KV_SM);

    const int n4 = M_TOTAL * D_MODEL / 4;

    // batched weight transpose
    WParams wp;
    wp.W[0] = Wq; wp.T[0] = (hf*)pWqh;
    wp.W[1] = Wk; wp.T[1] = (hf*)pWkh;
    wp.W[2] = Wv; wp.T[2] = (hf*)pWvh;
    wp.W[3] = Wo; wp.T[3] = (hf*)pWoh;
    convert_w_all<<<dim3(32, 32, 4), dim3(32, 8)>>>(wp);

    // batched A conversion (fp32 -> fp16, 3 inputs)
    AParams ap;
    ap.X[0] = queries; ap.H[0] = (hf*)pAh;
    ap.X[1] = keys;    ap.H[1] = (hf*)pA1;
    ap.X[2] = values;  ap.H[2] = (hf*)pA2;
    convert_a_all<<<dim3(n4 / 256, 1, 3), 256>>>(ap);

    zero_kernel<<<(NH * HD * HD + 255) / 256, 256>>>((float*)pKV, NH * HD * HD);

    // batched Q/K/V projections (fp16 A via cp.async, R11-proven mainloop)
    ProjParams pp;
    pp.A[0] = (hf*)pAh; pp.W[0] = (hf*)pWqh; pp.bias[0] = bq; pp.out[0] = (hf*)pQh;
    pp.A[1] = (hf*)pA1; pp.W[1] = (hf*)pWkh; pp.bias[1] = bk; pp.out[1] = (hf*)pKT;
    pp.A[2] = (hf*)pA2; pp.W[2] = (hf*)pWvh; pp.bias[2] = bv; pp.out[2] = (hf*)pVT;
    gemm_proj<<<dim3(8, 128, 3), 256, SM_TOTAL>>>(pp);

    // attention core (tensor-core)
    ksum_kernel<<<dim3(D_MODEL, N_BATCH), 128>>>((const hf*)pKT, (float*)pKS);
    kv_tc<<<dim3(NH, 8), 256, KV_SM>>>((const hf*)pVT, (const hf*)pKT, (float*)pKV);
    kvh_kernel<<<NH * HD * HD / 1024, 256>>>((const float*)pKV, (hf*)pKVh);
    attn_out_tc<<<dim3(SEQ / 128, NH), 256>>>((const hf*)pQh, (const hf*)pKVh,
                                              (const float*)pKS, (hf*)pAh);

    // output projection
    gemm_out<<<dim3(8, 128), 256, SM_TOTAL>>>((const hf*)pAh, (const hf*)pWoh, bo, out);
}